// round 5
// baseline (speedup 1.0000x reference)
#include <cuda_runtime.h>
#include <cstdint>

#define N_NODES 1000000
#define N_ELEMS 4000000
#define N_GROUPS (N_ELEMS / 4)

// ---------------- scratch (device globals; no allocs allowed) ----------------
// Packed node table: [gux.xyz | guz.xyz | gphi.xyz | phi | pad | pad], 48B stride.
__device__ __align__(16) float g_node[N_NODES * 12];
// Per-node accumulator: [F.xyz | M.xyz | X.xyz | pad3], 48B stride.
// Scatter = red.v4 (+0), red.v4 (+16), red.f32 (+32).
__device__ __align__(16) float g_acc[N_NODES * 12];

// 0: sum_rkin  1: L_sum  2: S_fext  3: S_fr  4: S_mr_free  5: S_mr_pin
// 6: n_fd  7: n_fr  8: n_pin
__device__ double g_sc[9];
__device__ unsigned int g_qmax_bits;
__device__ unsigned int g_lmax_bits;
__device__ int g_conn_is64;

// ---------------- helpers ----------------
__device__ __forceinline__ double warpSumD(double v) {
    #pragma unroll
    for (int o = 16; o > 0; o >>= 1) v += __shfl_down_sync(0xffffffffu, v, o);
    return v;
}
__device__ __forceinline__ float warpMaxF(float v) {
    #pragma unroll
    for (int o = 16; o > 0; o >>= 1) v = fmaxf(v, __shfl_down_sync(0xffffffffu, v, o));
    return v;
}
__device__ __forceinline__ void redAddV4(float* p, float a, float b, float c, float d) {
    asm volatile("red.global.add.v4.f32 [%0], {%1, %2, %3, %4};"
                 :: "l"(p), "f"(a), "f"(b), "f"(c), "f"(d) : "memory");
}
__device__ __forceinline__ void redAddF(float* p, float a) {
    asm volatile("red.global.add.f32 [%0], %1;" :: "l"(p), "f"(a) : "memory");
}

// ---------------- conn dtype detection ----------------
// int64 layout: odd 32-bit words are high halves of node ids (< 2^20) == 0.
__global__ void detect_conn_kernel(const unsigned int* __restrict__ conn_w)
{
    if (threadIdx.x == 0) {
        int all_odd_zero = 1;
        for (int k = 0; k < 64; ++k)
            if (conn_w[2 * k + 1] != 0u) { all_odd_zero = 0; break; }
        g_conn_is64 = all_odd_zero;
    }
}

// ---------------- node packing prologue ----------------
__global__ __launch_bounds__(256)
void pack_kernel(const float* __restrict__ phi,
                 const float* __restrict__ gux,
                 const float* __restrict__ guz,
                 const float* __restrict__ gphi)
{
    int n = blockIdx.x * blockDim.x + threadIdx.x;
    if (n >= N_NODES) return;
    size_t b = 3 * (size_t)n;
    float a0 = gux[b], a1 = gux[b + 1], a2 = gux[b + 2];
    float u0 = guz[b], u1 = guz[b + 1], u2 = guz[b + 2];
    float p0 = gphi[b], p1 = gphi[b + 1], p2 = gphi[b + 2];
    float ph = phi[n];
    float4* o = reinterpret_cast<float4*>(&g_node[12 * (size_t)n]);
    o[0] = make_float4(a0, a1, a2, u0);
    o[1] = make_float4(u1, u2, p0, p1);
    o[2] = make_float4(p2, ph, 0.0f, 0.0f);
}

// ---------------- element pass: 4 elements per thread, vector loads ----------
__global__ __launch_bounds__(256)
void elem_kernel(const float* __restrict__ pE,
                 const float* __restrict__ pA,
                 const float* __restrict__ pI,
                 const float* __restrict__ Lq,
                 const float* __restrict__ dirs,
                 const float* __restrict__ loads,
                 const int*   __restrict__ conn)
{
    const int is64 = g_conn_is64;
    const float4* nd = reinterpret_cast<const float4*>(g_node);
    const float4* dirs4  = reinterpret_cast<const float4*>(dirs);
    const float4* loads4 = reinterpret_cast<const float4*>(loads);
    const float4* E4p = reinterpret_cast<const float4*>(pE);
    const float4* A4p = reinterpret_cast<const float4*>(pA);
    const float4* I4p = reinterpret_cast<const float4*>(pI);
    const float4* L4p = reinterpret_cast<const float4*>(Lq);
    const int4*   c4  = reinterpret_cast<const int4*>(conn);

    int t = blockIdx.x * blockDim.x + threadIdx.x;
    if (t >= N_GROUPS) return;

    // ---- vector stream loads for 4 elements ----
    float4 d0 = dirs4[3 * (size_t)t], d1 = dirs4[3 * (size_t)t + 1], d2 = dirs4[3 * (size_t)t + 2];
    float4 q0 = loads4[3 * (size_t)t], q1 = loads4[3 * (size_t)t + 1], q2 = loads4[3 * (size_t)t + 2];
    float4 E4 = E4p[t], A4 = A4p[t], I4 = I4p[t], L4 = L4p[t];

    float xc[4][3] = {{d0.x, d0.y, d0.z}, {d0.w, d1.x, d1.y},
                      {d1.z, d1.w, d2.x}, {d2.y, d2.z, d2.w}};
    float lc[4][3] = {{q0.x, q0.y, q0.z}, {q0.w, q1.x, q1.y},
                      {q1.z, q1.w, q2.x}, {q2.y, q2.z, q2.w}};
    float Ev[4] = {E4.x, E4.y, E4.z, E4.w};
    float Av[4] = {A4.x, A4.y, A4.z, A4.w};
    float Iv[4] = {I4.x, I4.y, I4.z, I4.w};
    float Lv[4] = {L4.x, L4.y, L4.z, L4.w};

    int ii[4], jj[4];
    if (is64) {
        int4 c0 = c4[4 * (size_t)t], c1 = c4[4 * (size_t)t + 1];
        int4 c2 = c4[4 * (size_t)t + 2], c3 = c4[4 * (size_t)t + 3];
        ii[0] = c0.x; jj[0] = c0.z;  ii[1] = c1.x; jj[1] = c1.z;
        ii[2] = c2.x; jj[2] = c2.z;  ii[3] = c3.x; jj[3] = c3.z;
    } else {
        int4 c0 = c4[2 * (size_t)t], c1 = c4[2 * (size_t)t + 1];
        ii[0] = c0.x; jj[0] = c0.y;  ii[1] = c0.z; jj[1] = c0.w;
        ii[2] = c1.x; jj[2] = c1.y;  ii[3] = c1.z; jj[3] = c1.w;
    }

    double t_rkin = 0.0, t_Lsum = 0.0;
    float t_qmax = 0.0f, t_lmax = 0.0f;

    #pragma unroll
    for (int k = 0; k < 4; ++k) {
        float x0 = xc[k][0], x1 = xc[k][1], x2 = xc[k][2];
        int i = ii[k], j = jj[k];
        float L  = Lv[k];
        float EA = Ev[k] * Av[k];
        float EI = Ev[k] * Iv[k];

        // local axes
        float zx, zy, zz;
        if (fabsf(x1) > 0.99f) { zx = x1;  zy = -x0; zz = 0.0f; }
        else                   { zx = -x2; zy = 0.0f; zz = x0;  }
        float zinv = 1.0f / fmaxf(sqrtf(zx * zx + zy * zy + zz * zz), 1e-8f);
        zx *= zinv; zy *= zinv; zz *= zinv;
        float yx = zy * x2 - zz * x1;
        float yy = zz * x0 - zx * x2;
        float yz = zx * x1 - zy * x0;
        float yinv = 1.0f / fmaxf(sqrtf(yx * yx + yy * yy + yz * yz), 1e-8f);
        yx *= yinv; yy *= yinv; yz *= yinv;

        // packed gathers: 3 x LDG.128 per endpoint
        float4 Gi0 = nd[3 * (size_t)i], Gi1 = nd[3 * (size_t)i + 1], Gi2 = nd[3 * (size_t)i + 2];
        float4 Gj0 = nd[3 * (size_t)j], Gj1 = nd[3 * (size_t)j + 1], Gj2 = nd[3 * (size_t)j + 2];

        float gux_i = Gi0.x * x0 + Gi0.y * x1 + Gi0.z * x2;
        float guz_i = Gi0.w * x0 + Gi1.x * x1 + Gi1.y * x2;
        float kap_i = Gi1.z * x0 + Gi1.w * x1 + Gi2.x * x2;
        float phi_i = Gi2.y;
        float gux_j = Gj0.x * x0 + Gj0.y * x1 + Gj0.z * x2;
        float guz_j = Gj0.w * x0 + Gj1.x * x1 + Gj1.y * x2;
        float kap_j = Gj1.z * x0 + Gj1.w * x1 + Gj2.x * x2;
        float phi_j = Gj2.y;

        float eps_i = x0 * gux_i + x2 * guz_i;
        float eps_j = x0 * gux_j + x2 * guz_j;
        float Navg  = 0.5f * EA * (eps_i + eps_j);
        float Mi = EI * kap_i;
        float Mj = EI * kap_j;
        float V  = (Mj - Mi) / L;

        float Fx = Navg * x0 + V * zx;
        float Fy = Navg * x1 + V * zy;
        float Fz = Navg * x2 + V * zz;

        float l0 = lc[k][0], l1 = lc[k][1], l2 = lc[k][2];
        float hl = 0.5f * L;
        float X0 = l0 * hl, X1 = l1 * hl, X2 = l2 * hl;

        float* ai = &g_acc[12 * (size_t)i];
        float* aj = &g_acc[12 * (size_t)j];
        redAddV4(ai,      Fx,  Fy,  Fz, Mi * yx);
        redAddV4(ai + 4,  Mi * yy, Mi * yz, X0, X1);
        redAddF (ai + 8,  X2);
        redAddV4(aj,     -Fx, -Fy, -Fz, Mj * yx);
        redAddV4(aj + 4,  Mj * yy, Mj * yz, X0, X1);
        redAddF (aj + 8,  X2);

        // kinematics
        float du_i = zx * gux_i + zz * guz_i;
        float du_j = zx * gux_j + zz * guz_j;
        float ri = phi_i - du_i;
        float rj = phi_j - du_j;
        t_rkin += (double)(ri * ri) + (double)(rj * rj);

        t_Lsum += (double)L;
        t_lmax  = fmaxf(t_lmax, L);
        t_qmax  = fmaxf(t_qmax, fmaxf(fabsf(l0), fmaxf(fabsf(l1), fabsf(l2))));
    }

    t_rkin = warpSumD(t_rkin);
    t_Lsum = warpSumD(t_Lsum);
    t_qmax = warpMaxF(t_qmax);
    t_lmax = warpMaxF(t_lmax);
    if ((threadIdx.x & 31) == 0) {
        atomicAdd(&g_sc[0], t_rkin);
        atomicAdd(&g_sc[1], t_Lsum);
        atomicMax(&g_qmax_bits, __float_as_uint(t_qmax));
        atomicMax(&g_lmax_bits, __float_as_uint(t_lmax));
    }
}

// ---------------- node pass ----------------
__global__ __launch_bounds__(256)
void node_kernel(const float* __restrict__ bc_disp,
                 const float* __restrict__ bc_rot)
{
    double t_sfext = 0.0, t_sfr = 0.0, t_smrf = 0.0, t_smrp = 0.0;
    double t_nfd = 0.0, t_nfr = 0.0, t_npin = 0.0;

    const float4* A4 = reinterpret_cast<const float4*>(g_acc);

    for (int n = blockIdx.x * blockDim.x + threadIdx.x; n < N_NODES;
         n += gridDim.x * blockDim.x) {
        float bd = bc_disp[n];
        float br = bc_rot[n];
        bool fd  = bd < 0.5f;
        bool fr  = br < 0.5f;
        bool pin = (bd > 0.5f) && (br < 0.5f);

        float4 a0 = A4[3 * (size_t)n];
        float4 a1 = A4[3 * (size_t)n + 1];
        float x2v = g_acc[12 * (size_t)n + 8];

        // F = a0.xyz, M = (a0.w, a1.x, a1.y), X = (a1.z, a1.w, x2v)
        float fex2 = a1.z * a1.z + a1.w * a1.w + x2v * x2v;
        float rx = a0.x + a1.z, ry = a0.y + a1.w, rz = a0.z + x2v;
        float fr2  = rx * rx + ry * ry + rz * rz;
        float m2   = a0.w * a0.w + a1.x * a1.x + a1.y * a1.y;

        if (fd)  { t_nfd  += 1.0; t_sfext += (double)fex2; t_sfr += (double)fr2; }
        if (fr)  { t_nfr  += 1.0; t_smrf  += (double)m2; }
        if (pin) { t_npin += 1.0; t_smrp  += (double)m2; }
    }

    t_sfext = warpSumD(t_sfext);
    t_sfr   = warpSumD(t_sfr);
    t_smrf  = warpSumD(t_smrf);
    t_smrp  = warpSumD(t_smrp);
    t_nfd   = warpSumD(t_nfd);
    t_nfr   = warpSumD(t_nfr);
    t_npin  = warpSumD(t_npin);
    if ((threadIdx.x & 31) == 0) {
        atomicAdd(&g_sc[2], t_sfext);
        atomicAdd(&g_sc[3], t_sfr);
        atomicAdd(&g_sc[4], t_smrf);
        atomicAdd(&g_sc[5], t_smrp);
        atomicAdd(&g_sc[6], t_nfd);
        atomicAdd(&g_sc[7], t_nfr);
        atomicAdd(&g_sc[8], t_npin);
    }
}

// ---------------- finalize ----------------
__global__ void finalize_kernel(float* __restrict__ out)
{
    double sum_rkin = g_sc[0];
    double L_sum    = g_sc[1];
    double S_fext   = g_sc[2];
    double S_fr     = g_sc[3];
    double S_mrf    = g_sc[4];
    double S_mrp    = g_sc[5];
    double n_fd     = g_sc[6];
    double n_fr     = g_sc[7];
    double n_pin    = g_sc[8];
    float qmax = __uint_as_float(g_qmax_bits);
    float lmax = __uint_as_float(g_lmax_bits);

    double nfd = fmax(n_fd, 1.0);
    double F_char = fmax(sqrt(S_fext / (3.0 * nfd)), 1.0);
    double L_force = S_fr / (F_char * F_char * 3.0 * nfd);

    double q_max = fmax((double)qmax, 1.0);
    double M_char = fmax(q_max * (double)lmax * L_sum / 8.0, 1.0);
    double M2 = M_char * M_char;

    double nfr = fmax(n_fr, 1.0);
    double L_moment = S_mrf / (M2 * 3.0 * nfr);

    double L_neumann = 0.0;
    if (n_pin > 0.0) {
        L_neumann = S_mrp / (M2 * 3.0 * fmax(n_pin, 1.0));
    }

    double L_kin = 0.5 * (sum_rkin / (double)N_ELEMS);

    double total = 1.0 * L_force + 1.0 * L_moment + 1.0 * L_neumann + 0.1 * L_kin;
    out[0] = (float)total;
}

// ---------------- launch ----------------
extern "C" void kernel_launch(void* const* d_in, const int* in_sizes, int n_in,
                              void* d_out, int out_size)
{
    const float* phi   = (const float*)d_in[0];
    const float* gux   = (const float*)d_in[1];
    const float* guz   = (const float*)d_in[2];
    const float* gphi  = (const float*)d_in[3];
    const float* pE    = (const float*)d_in[4];
    const float* pA    = (const float*)d_in[5];
    const float* pI    = (const float*)d_in[6];
    const float* Lq    = (const float*)d_in[7];
    const float* dirs  = (const float*)d_in[8];
    const float* loads = (const float*)d_in[9];
    const float* bcd   = (const float*)d_in[10];
    const float* bcr   = (const float*)d_in[11];
    const int*   conn  = (const int*)d_in[12];
    float* out = (float*)d_out;

    void *pAcc, *pS, *pQ, *pL;
    cudaGetSymbolAddress(&pAcc, g_acc);
    cudaGetSymbolAddress(&pS, g_sc);
    cudaGetSymbolAddress(&pQ, g_qmax_bits);
    cudaGetSymbolAddress(&pL, g_lmax_bits);

    cudaMemsetAsync(pAcc, 0, N_NODES * 12 * sizeof(float), 0);
    cudaMemsetAsync(pS, 0, 9 * sizeof(double), 0);
    cudaMemsetAsync(pQ, 0, sizeof(unsigned int), 0);
    cudaMemsetAsync(pL, 0, sizeof(unsigned int), 0);

    detect_conn_kernel<<<1, 32>>>((const unsigned int*)conn);
    pack_kernel<<<(N_NODES + 255) / 256, 256>>>(phi, gux, guz, gphi);
    elem_kernel<<<(N_GROUPS + 255) / 256, 256>>>(pE, pA, pI, Lq, dirs, loads, conn);
    node_kernel<<<1184, 256>>>(bcd, bcr);
    finalize_kernel<<<1, 1>>>(out);
}